// round 9
// baseline (speedup 1.0000x reference)
#include <cuda_runtime.h>
#include <cuda_fp16.h>
#include <math.h>
#include <stdint.h>

#define N_NODES 50000
#define N_EDGES 800000
#define F       128      // HEADS*HID
#define HEADS   4
#define HID     32
#define NEG_SLOPE 0.2f
#define MTILE   80       // 50000 = 625 * 80
#define SCAN_BLK 512
#define NSCAN ((N_NODES + SCAN_BLK - 1) / SCAN_BLK)   // 98

// ---------------- device-global scratch (no allocations allowed) -------------
__device__ __align__(16) __half g_hh [N_NODES * F];   // h = x @ W (fp16)
__device__ __align__(16) __half g_xh [N_NODES * F];   // layer-1 input, fp16
__device__ __align__(16) __half g_x2h[N_NODES * F];   // layer-1 output, fp16
__device__ __align__(16) float  g_el [N_NODES * HEADS];
__device__ __align__(16) float  g_er [N_NODES * HEADS];
// B fragments, fp16, paired n-tiles: for kk (0..7), p (0..7), lane (0..31):
//   uint4{ b(nt=2p).c0, b(2p).c1, b(2p+1).c0, b(2p+1).c1 }
__device__ __align__(16) uint4  g_Bfrag[8 * 8 * 32];
__device__ unsigned g_deg[N_NODES];                    // zero-init; scan3 re-zeroes
__device__ unsigned g_off[N_NODES + 1];
__device__ unsigned g_cur[N_NODES];
__device__ unsigned g_part[NSCAN];
__device__ int      g_csr_src[N_EDGES];               // src ids grouped by dst

// ---------------- helpers -----------------------------------------------------
__device__ __forceinline__ unsigned pack_h2(float x0, float x1) {
    __half2 h = __floats2half2_rn(x0, x1);
    return *(unsigned*)&h;
}
__device__ __forceinline__ void mma_f16(float4& d,
                                        unsigned a0, unsigned a1, unsigned a2, unsigned a3,
                                        unsigned b0, unsigned b1) {
    asm volatile("mma.sync.aligned.m16n8k16.row.col.f32.f16.f16.f32 "
                 "{%0,%1,%2,%3}, {%4,%5,%6,%7}, {%8,%9}, {%0,%1,%2,%3};"
                 : "+f"(d.x), "+f"(d.y), "+f"(d.z), "+f"(d.w)
                 : "r"(a0), "r"(a1), "r"(a2), "r"(a3), "r"(b0), "r"(b1));
}
__device__ __forceinline__ void ldsm_x4(unsigned& a0, unsigned& a1, unsigned& a2, unsigned& a3,
                                        uint32_t addr) {
    asm volatile("ldmatrix.sync.aligned.m8n8.x4.shared.b16 {%0,%1,%2,%3}, [%4];"
                 : "=r"(a0), "=r"(a1), "=r"(a2), "=r"(a3) : "r"(addr));
}

// ---------------- fp32 -> fp16 convert (layer-1 input) ------------------------
__global__ void conv_half_kernel(const float* __restrict__ x) {
    int i = blockIdx.x * blockDim.x + threadIdx.x;
    if (i >= N_NODES * F / 4) return;
    float4 v = ((const float4*)x)[i];
    uint2 u;
    u.x = pack_h2(v.x, v.y); u.y = pack_h2(v.z, v.w);
    ((uint2*)g_xh)[i] = u;
}

// ---------------- CSR build ---------------------------------------------------
__global__ void hist_kernel(const int* __restrict__ dst) {
    int e = blockIdx.x * blockDim.x + threadIdx.x;
    if (e < N_EDGES) atomicAdd(&g_deg[dst[e]], 1u);
}

__global__ void scan1_kernel() {        // per-block reduce of g_deg
    __shared__ unsigned s[SCAN_BLK];
    int t = threadIdx.x, i = blockIdx.x * SCAN_BLK + t;
    s[t] = (i < N_NODES) ? g_deg[i] : 0u;
    __syncthreads();
    for (int o = SCAN_BLK / 2; o > 0; o >>= 1) {
        if (t < o) s[t] += s[t + o];
        __syncthreads();
    }
    if (t == 0) g_part[blockIdx.x] = s[0];
}

__global__ void scan2_kernel() {        // scan the 98 partials (1 block)
    __shared__ unsigned s[128];
    int t = threadIdx.x;
    unsigned v = (t < NSCAN) ? g_part[t] : 0u;
    s[t] = v; __syncthreads();
    for (int o = 1; o < 128; o <<= 1) {
        unsigned u = (t >= o) ? s[t - o] : 0u;
        __syncthreads();
        s[t] += u;
        __syncthreads();
    }
    if (t < NSCAN) g_part[t] = s[t] - v;          // exclusive
    if (t == 0) g_off[N_NODES] = N_EDGES;
}

__global__ void scan3_kernel() {        // block scan + base; re-zero g_deg
    __shared__ unsigned s[SCAN_BLK];
    int t = threadIdx.x, i = blockIdx.x * SCAN_BLK + t;
    unsigned v = (i < N_NODES) ? g_deg[i] : 0u;
    s[t] = v; __syncthreads();
    for (int o = 1; o < SCAN_BLK; o <<= 1) {
        unsigned u = (t >= o) ? s[t - o] : 0u;
        __syncthreads();
        s[t] += u;
        __syncthreads();
    }
    if (i < N_NODES) {
        unsigned excl = s[t] - v + g_part[blockIdx.x];
        g_off[i] = excl; g_cur[i] = excl;
        g_deg[i] = 0u;
    }
}

__global__ void scatter_kernel(const int* __restrict__ src, const int* __restrict__ dst) {
    int e = blockIdx.x * blockDim.x + threadIdx.x;
    if (e >= N_EDGES) return;
    unsigned pos = atomicAdd(&g_cur[dst[e]], 1u);
    g_csr_src[pos] = src[e];
}

// ---------------- W -> fp16 fragment layout (m16n8k16, paired n-tiles) --------
__global__ void bfrag_kernel(const float* __restrict__ W) {
    int idx = blockIdx.x * blockDim.x + threadIdx.x;
    if (idx >= 8 * 8 * 32) return;
    int lane = idx & 31, p = (idx >> 5) & 7, kk = idx >> 8;
    int g = lane >> 2, tig = lane & 3;
    int k0 = kk * 16 + 2 * tig;
    int k1 = k0 + 8;
    int n0 = (2 * p) * 8 + g;
    int n1 = (2 * p + 1) * 8 + g;
    uint4 o;
    o.x = pack_h2(W[k0 * 128 + n0], W[(k0 + 1) * 128 + n0]);
    o.y = pack_h2(W[k1 * 128 + n0], W[(k1 + 1) * 128 + n0]);
    o.z = pack_h2(W[k0 * 128 + n1], W[(k0 + 1) * 128 + n1]);
    o.w = pack_h2(W[k1 * 128 + n1], W[(k1 + 1) * 128 + n1]);
    g_Bfrag[idx] = o;
}

// ---------------- tensor-core GEMM (fp16 A via ldmatrix) + fused el/er --------
// 320 threads (10 warps), tile 80x128, pure fp16 mma: 64 HMMA/warp.
#define XSTRIDE 136      // halves per row (8-half pad => conflict-free ldmatrix)
__global__ __launch_bounds__(320) void gemm_mma_kernel(
        const __half* __restrict__ x,
        const float* __restrict__ al, const float* __restrict__ ar) {
    __shared__ __half xs[MTILE * XSTRIDE];
    const int tid = threadIdx.x, wid = tid >> 5, lane = tid & 31;
    const int g = lane >> 2, tig = lane & 3;
    const int base = blockIdx.x * MTILE;

    for (int q = tid; q < MTILE * 16; q += 320) {
        int row = q >> 4, c8 = q & 15;
        uint4 v = ((const uint4*)(x + (size_t)(base + row) * F))[c8];
        *(uint4*)&xs[row * XSTRIDE + c8 * 8] = v;
    }
    __syncthreads();

    const int warpM = wid >> 1, warpN = wid & 1;
    const int rowbase = warpM * 16;

    const int lrow = rowbase + ((lane >> 3) & 1) * 8 + (lane & 7);
    uint32_t abase = (uint32_t)__cvta_generic_to_shared(xs)
                   + lrow * (XSTRIDE * 2) + (lane >> 4) * 16;

    float4 acc[8];
    #pragma unroll
    for (int j = 0; j < 8; j++) acc[j] = make_float4(0.f, 0.f, 0.f, 0.f);

    #pragma unroll
    for (int kk = 0; kk < 8; kk++) {
        unsigned a0, a1, a2, a3;
        ldsm_x4(a0, a1, a2, a3, abase + kk * 32);
        const uint4* bp = g_Bfrag + (size_t)(kk * 8 + warpN * 4) * 32 + lane;
        #pragma unroll
        for (int jp = 0; jp < 4; jp++) {
            uint4 b = bp[jp * 32];        // {b(2jp).c0, b(2jp).c1, b(2jp+1).c0, b(2jp+1).c1}
            mma_f16(acc[2 * jp + 0], a0, a1, a2, a3, b.x, b.y);
            mma_f16(acc[2 * jp + 1], a0, a1, a2, a3, b.z, b.w);
        }
    }

    // epilogue: store h (fp16) and reduce el/er per row,head
    const int r0 = base + rowbase + g, r1 = r0 + 8;
    float pel[2][2] = {{0.f,0.f},{0.f,0.f}};
    float per[2][2] = {{0.f,0.f},{0.f,0.f}};

    #pragma unroll
    for (int j = 0; j < 8; j++) {
        int col = warpN * 64 + j * 8 + 2 * tig;
        float al0 = al[col], al1 = al[col + 1];
        float ar0 = ar[col], ar1 = ar[col + 1];
        int hh = j >> 2;
        pel[hh][0] += acc[j].x * al0 + acc[j].y * al1;
        pel[hh][1] += acc[j].z * al0 + acc[j].w * al1;
        per[hh][0] += acc[j].x * ar0 + acc[j].y * ar1;
        per[hh][1] += acc[j].z * ar0 + acc[j].w * ar1;
        *(__half2*)(g_hh + (size_t)r0 * F + col) = __floats2half2_rn(acc[j].x, acc[j].y);
        *(__half2*)(g_hh + (size_t)r1 * F + col) = __floats2half2_rn(acc[j].z, acc[j].w);
    }
    #pragma unroll
    for (int o = 1; o < 4; o <<= 1) {
        #pragma unroll
        for (int hh = 0; hh < 2; hh++) {
            #pragma unroll
            for (int rr = 0; rr < 2; rr++) {
                pel[hh][rr] += __shfl_xor_sync(0xffffffffu, pel[hh][rr], o);
                per[hh][rr] += __shfl_xor_sync(0xffffffffu, per[hh][rr], o);
            }
        }
    }
    if (tig == 0) {
        #pragma unroll
        for (int hh = 0; hh < 2; hh++) {
            int head = warpN * 2 + hh;
            g_el[r0 * HEADS + head] = pel[hh][0];
            g_el[r1 * HEADS + head] = pel[hh][1];
            g_er[r0 * HEADS + head] = per[hh][0];
            g_er[r1 * HEADS + head] = per[hh][1];
        }
    }
}

// ---------------- fused edge softmax + aggregation (gather, no max pass) ------
__device__ __forceinline__ float leaky_exp(float e) {
    e = e > 0.f ? e : NEG_SLOPE * e;
    return __expf(e);
}
__device__ __forceinline__ void acc_edge(float4& acc, float a, uint2 v) {
    float2 f01 = __half22float2(*(__half2*)&v.x);
    float2 f23 = __half22float2(*(__half2*)&v.y);
    acc.x = fmaf(a, f01.x, acc.x);
    acc.y = fmaf(a, f01.y, acc.y);
    acc.z = fmaf(a, f23.x, acc.z);
    acc.w = fmaf(a, f23.y, acc.w);
}

template<bool FP16OUT>
__global__ void gat_agg_kernel(const float* __restrict__ bias, float* __restrict__ out,
                               __half* __restrict__ out_h) {
    int warp = (blockIdx.x * blockDim.x + threadIdx.x) >> 5;
    int lane = threadIdx.x & 31;
    if (warp >= N_NODES) return;

    const unsigned start = g_off[warp];
    const int deg = (int)(g_off[warp + 1] - start);
    const int head = lane >> 3;
    const float erh = g_er[warp * 4 + head];
    const __half* __restrict__ hh = g_hh;

    float4 acc = make_float4(0.f, 0.f, 0.f, 0.f);
    float denom = 0.f;

    // predicated 8-wide chunks: tail keeps MLP=8, inactive lanes issue no loads
    for (int i = 0; i < deg; i += 8) {
        int s[8];
        float a[8];
        uint2 v[8];
        #pragma unroll
        for (int u = 0; u < 8; u++) {
            bool ok = (i + u) < deg;
            s[u] = ok ? g_csr_src[start + i + u] : -1;
        }
        #pragma unroll
        for (int u = 0; u < 8; u++) {
            if (s[u] >= 0) {
                a[u] = g_el[s[u] * 4 + head];
                v[u] = *(const uint2*)(hh + (size_t)s[u] * F + lane * 4);
            } else {
                a[u] = 0.f;
                v[u] = make_uint2(0u, 0u);
            }
        }
        #pragma unroll
        for (int u = 0; u < 8; u++) {
            float au = (s[u] >= 0) ? leaky_exp(a[u] + erh) : 0.f;
            denom += au;
            acc_edge(acc, au, v[u]);
        }
    }

    const float inv = 1.0f / fmaxf(denom, 1e-9f);
    const float4 b4 = ((const float4*)bias)[lane];
    float4 r;
    r.x = acc.x * inv + b4.x; r.x = r.x > 0.f ? r.x : expm1f(r.x);
    r.y = acc.y * inv + b4.y; r.y = r.y > 0.f ? r.y : expm1f(r.y);
    r.z = acc.z * inv + b4.z; r.z = r.z > 0.f ? r.z : expm1f(r.z);
    r.w = acc.w * inv + b4.w; r.w = r.w > 0.f ? r.w : expm1f(r.w);

    if (FP16OUT) {
        uint2 u;
        u.x = pack_h2(r.x, r.y); u.y = pack_h2(r.z, r.w);
        *(uint2*)(out_h + (size_t)warp * F + lane * 4) = u;
    } else {
        *(float4*)(out + (size_t)warp * F + lane * 4) = r;
    }
}

// ---------------- host orchestration -----------------------------------------

extern "C" void kernel_launch(void* const* d_in, const int* in_sizes, int n_in,
                              void* d_out, int out_size) {
    const float* features = (const float*)d_in[0];
    const int*   src      = (const int*)  d_in[1];
    const int*   dst      = (const int*)  d_in[2];
    const float* W1       = (const float*)d_in[3];
    const float* al1      = (const float*)d_in[4];
    const float* ar1      = (const float*)d_in[5];
    const float* b1       = (const float*)d_in[6];
    const float* W2       = (const float*)d_in[7];
    const float* al2      = (const float*)d_in[8];
    const float* ar2      = (const float*)d_in[9];
    const float* b2       = (const float*)d_in[10];
    float* out = (float*)d_out;

    __half* xh = nullptr;  cudaGetSymbolAddress((void**)&xh,  g_xh);
    __half* x2h = nullptr; cudaGetSymbolAddress((void**)&x2h, g_x2h);

    // slot 4 = gemm1 (ncu capture target)
    conv_half_kernel<<<(N_NODES * F / 4 + 255) / 256, 256>>>(features);   // 1
    bfrag_kernel<<<8, 256>>>(W1);                                         // 2
    hist_kernel<<<(N_EDGES + 255) / 256, 256>>>(dst);                     // 3
    gemm_mma_kernel<<<N_NODES / MTILE, 320>>>(xh, al1, ar1);              // 4 <- profiled
    scan1_kernel<<<NSCAN, SCAN_BLK>>>();                                  // 5
    scan2_kernel<<<1, 128>>>();                                           // 6
    scan3_kernel<<<NSCAN, SCAN_BLK>>>();                                  // 7
    scatter_kernel<<<(N_EDGES + 255) / 256, 256>>>(src, dst);             // 8
    gat_agg_kernel<true><<<(N_NODES * 32 + 255) / 256, 256>>>(b1, nullptr, x2h);  // 9
    bfrag_kernel<<<8, 256>>>(W2);                                         // 10
    gemm_mma_kernel<<<N_NODES / MTILE, 320>>>(x2h, al2, ar2);             // 11
    gat_agg_kernel<false><<<(N_NODES * 32 + 255) / 256, 256>>>(b2, out, nullptr); // 12
}

// round 11
// speedup vs baseline: 1.1749x; 1.1749x over previous
#include <cuda_runtime.h>
#include <cuda_fp16.h>
#include <math.h>
#include <stdint.h>

#define N_NODES 50000
#define N_EDGES 800000
#define F       128      // HEADS*HID
#define HEADS   4
#define HID     32
#define NEG_SLOPE 0.2f
#define MTILE   80       // 50000 = 625 * 80
#define SCAN_BLK 512
#define NSCAN ((N_NODES + SCAN_BLK - 1) / SCAN_BLK)   // 98

// ---------------- device-global scratch (no allocations allowed) -------------
__device__ __align__(16) __half g_hh [N_NODES * F];   // h = x @ W (fp16)
__device__ __align__(16) __half g_xh [N_NODES * F];   // layer-1 input, fp16
__device__ __align__(16) __half g_x2h[N_NODES * F];   // layer-1 output, fp16
__device__ __align__(16) float  g_el [N_NODES * HEADS];
__device__ __align__(16) float  g_er [N_NODES * HEADS];
// B fragments, fp16, paired n-tiles: for kk (0..7), p (0..7), lane (0..31):
//   uint4{ b(nt=2p).c0, b(2p).c1, b(2p+1).c0, b(2p+1).c1 }
__device__ __align__(16) uint4  g_Bfrag[8 * 8 * 32];
__device__ unsigned g_deg[N_NODES];                    // zero-init; scan3 re-zeroes
__device__ unsigned g_off[N_NODES + 1];
__device__ unsigned g_cur[N_NODES];
__device__ unsigned g_part[NSCAN];
__device__ int      g_csr_src[N_EDGES];               // src ids grouped by dst

// ---------------- helpers -----------------------------------------------------
__device__ __forceinline__ unsigned pack_h2(float x0, float x1) {
    __half2 h = __floats2half2_rn(x0, x1);
    return *(unsigned*)&h;
}
__device__ __forceinline__ void mma_f16(float4& d,
                                        unsigned a0, unsigned a1, unsigned a2, unsigned a3,
                                        unsigned b0, unsigned b1) {
    asm volatile("mma.sync.aligned.m16n8k16.row.col.f32.f16.f16.f32 "
                 "{%0,%1,%2,%3}, {%4,%5,%6,%7}, {%8,%9}, {%0,%1,%2,%3};"
                 : "+f"(d.x), "+f"(d.y), "+f"(d.z), "+f"(d.w)
                 : "r"(a0), "r"(a1), "r"(a2), "r"(a3), "r"(b0), "r"(b1));
}
__device__ __forceinline__ void ldsm_x4(unsigned& a0, unsigned& a1, unsigned& a2, unsigned& a3,
                                        uint32_t addr) {
    asm volatile("ldmatrix.sync.aligned.m8n8.x4.shared.b16 {%0,%1,%2,%3}, [%4];"
                 : "=r"(a0), "=r"(a1), "=r"(a2), "=r"(a3) : "r"(addr));
}

// ---------------- fp32 -> fp16 convert (layer-1 input) ------------------------
__global__ void conv_half_kernel(const float* __restrict__ x) {
    int i = blockIdx.x * blockDim.x + threadIdx.x;
    if (i >= N_NODES * F / 4) return;
    float4 v = ((const float4*)x)[i];
    uint2 u;
    u.x = pack_h2(v.x, v.y); u.y = pack_h2(v.z, v.w);
    ((uint2*)g_xh)[i] = u;
}

// ---------------- CSR build ---------------------------------------------------
__global__ void hist_kernel(const int* __restrict__ dst) {
    int e = blockIdx.x * blockDim.x + threadIdx.x;
    if (e < N_EDGES) atomicAdd(&g_deg[dst[e]], 1u);
}

__global__ void scan1_kernel() {        // per-block reduce of g_deg
    __shared__ unsigned s[SCAN_BLK];
    int t = threadIdx.x, i = blockIdx.x * SCAN_BLK + t;
    s[t] = (i < N_NODES) ? g_deg[i] : 0u;
    __syncthreads();
    for (int o = SCAN_BLK / 2; o > 0; o >>= 1) {
        if (t < o) s[t] += s[t + o];
        __syncthreads();
    }
    if (t == 0) g_part[blockIdx.x] = s[0];
}

__global__ void scan2_kernel() {        // scan the 98 partials (1 block)
    __shared__ unsigned s[128];
    int t = threadIdx.x;
    unsigned v = (t < NSCAN) ? g_part[t] : 0u;
    s[t] = v; __syncthreads();
    for (int o = 1; o < 128; o <<= 1) {
        unsigned u = (t >= o) ? s[t - o] : 0u;
        __syncthreads();
        s[t] += u;
        __syncthreads();
    }
    if (t < NSCAN) g_part[t] = s[t] - v;          // exclusive
    if (t == 0) g_off[N_NODES] = N_EDGES;
}

__global__ void scan3_kernel() {        // block scan + base; re-zero g_deg
    __shared__ unsigned s[SCAN_BLK];
    int t = threadIdx.x, i = blockIdx.x * SCAN_BLK + t;
    unsigned v = (i < N_NODES) ? g_deg[i] : 0u;
    s[t] = v; __syncthreads();
    for (int o = 1; o < SCAN_BLK; o <<= 1) {
        unsigned u = (t >= o) ? s[t - o] : 0u;
        __syncthreads();
        s[t] += u;
        __syncthreads();
    }
    if (i < N_NODES) {
        unsigned excl = s[t] - v + g_part[blockIdx.x];
        g_off[i] = excl; g_cur[i] = excl;
        g_deg[i] = 0u;
    }
}

__global__ void scatter_kernel(const int* __restrict__ src, const int* __restrict__ dst) {
    int e = blockIdx.x * blockDim.x + threadIdx.x;
    if (e >= N_EDGES) return;
    unsigned pos = atomicAdd(&g_cur[dst[e]], 1u);
    g_csr_src[pos] = src[e];
}

// ---------------- W -> fp16 fragment layout (m16n8k16, paired n-tiles) --------
__global__ void bfrag_kernel(const float* __restrict__ W) {
    int idx = blockIdx.x * blockDim.x + threadIdx.x;
    if (idx >= 8 * 8 * 32) return;
    int lane = idx & 31, p = (idx >> 5) & 7, kk = idx >> 8;
    int g = lane >> 2, tig = lane & 3;
    int k0 = kk * 16 + 2 * tig;
    int k1 = k0 + 8;
    int n0 = (2 * p) * 8 + g;
    int n1 = (2 * p + 1) * 8 + g;
    uint4 o;
    o.x = pack_h2(W[k0 * 128 + n0], W[(k0 + 1) * 128 + n0]);
    o.y = pack_h2(W[k1 * 128 + n0], W[(k1 + 1) * 128 + n0]);
    o.z = pack_h2(W[k0 * 128 + n1], W[(k0 + 1) * 128 + n1]);
    o.w = pack_h2(W[k1 * 128 + n1], W[(k1 + 1) * 128 + n1]);
    g_Bfrag[idx] = o;
}

// ---------------- tensor-core GEMM (fp16 A via ldmatrix) + fused el/er --------
// 320 threads (10 warps), tile 80x128, pure fp16 mma: 64 HMMA/warp.
// Epilogue stages h through smem for coalesced 16B global stores.
#define XSTRIDE 136      // halves per row (8-half pad => conflict-free ldmatrix/STS)
__global__ __launch_bounds__(320) void gemm_mma_kernel(
        const __half* __restrict__ x,
        const float* __restrict__ al, const float* __restrict__ ar) {
    __shared__ __half xs[MTILE * XSTRIDE];
    const int tid = threadIdx.x, wid = tid >> 5, lane = tid & 31;
    const int g = lane >> 2, tig = lane & 3;
    const int base = blockIdx.x * MTILE;

    for (int q = tid; q < MTILE * 16; q += 320) {
        int row = q >> 4, c8 = q & 15;
        uint4 v = ((const uint4*)(x + (size_t)(base + row) * F))[c8];
        *(uint4*)&xs[row * XSTRIDE + c8 * 8] = v;
    }
    __syncthreads();

    const int warpM = wid >> 1, warpN = wid & 1;
    const int rowbase = warpM * 16;

    const int lrow = rowbase + ((lane >> 3) & 1) * 8 + (lane & 7);
    uint32_t abase = (uint32_t)__cvta_generic_to_shared(xs)
                   + lrow * (XSTRIDE * 2) + (lane >> 4) * 16;

    float4 acc[8];
    #pragma unroll
    for (int j = 0; j < 8; j++) acc[j] = make_float4(0.f, 0.f, 0.f, 0.f);

    #pragma unroll
    for (int kk = 0; kk < 8; kk++) {
        unsigned a0, a1, a2, a3;
        ldsm_x4(a0, a1, a2, a3, abase + kk * 32);
        const uint4* bp = g_Bfrag + (size_t)(kk * 8 + warpN * 4) * 32 + lane;
        #pragma unroll
        for (int jp = 0; jp < 4; jp++) {
            uint4 b = bp[jp * 32];        // {b(2jp).c0, b(2jp).c1, b(2jp+1).c0, b(2jp+1).c1}
            mma_f16(acc[2 * jp + 0], a0, a1, a2, a3, b.x, b.y);
            mma_f16(acc[2 * jp + 1], a0, a1, a2, a3, b.z, b.w);
        }
    }

    // ---- epilogue ----
    // el/er partial dots from registers
    const int r0 = base + rowbase + g, r1 = r0 + 8;
    float pel[2][2] = {{0.f,0.f},{0.f,0.f}};
    float per[2][2] = {{0.f,0.f},{0.f,0.f}};
    #pragma unroll
    for (int j = 0; j < 8; j++) {
        int col = warpN * 64 + j * 8 + 2 * tig;
        float al0 = al[col], al1 = al[col + 1];
        float ar0 = ar[col], ar1 = ar[col + 1];
        int hh = j >> 2;
        pel[hh][0] += acc[j].x * al0 + acc[j].y * al1;
        pel[hh][1] += acc[j].z * al0 + acc[j].w * al1;
        per[hh][0] += acc[j].x * ar0 + acc[j].y * ar1;
        per[hh][1] += acc[j].z * ar0 + acc[j].w * ar1;
    }
    #pragma unroll
    for (int o = 1; o < 4; o <<= 1) {
        #pragma unroll
        for (int hh = 0; hh < 2; hh++) {
            #pragma unroll
            for (int rr = 0; rr < 2; rr++) {
                pel[hh][rr] += __shfl_xor_sync(0xffffffffu, pel[hh][rr], o);
                per[hh][rr] += __shfl_xor_sync(0xffffffffu, per[hh][rr], o);
            }
        }
    }
    if (tig == 0) {
        #pragma unroll
        for (int hh = 0; hh < 2; hh++) {
            int head = warpN * 2 + hh;
            g_el[r0 * HEADS + head] = pel[hh][0];
            g_el[r1 * HEADS + head] = pel[hh][1];
            g_er[r0 * HEADS + head] = per[hh][0];
            g_er[r1 * HEADS + head] = per[hh][1];
        }
    }

    // stage h into smem (A tile no longer needed), then coalesced flush
    __syncthreads();
    {
        const int lr0 = rowbase + g, lr1 = lr0 + 8;
        #pragma unroll
        for (int j = 0; j < 8; j++) {
            int col = warpN * 64 + j * 8 + 2 * tig;
            *(__half2*)&xs[lr0 * XSTRIDE + col] = __floats2half2_rn(acc[j].x, acc[j].y);
            *(__half2*)&xs[lr1 * XSTRIDE + col] = __floats2half2_rn(acc[j].z, acc[j].w);
        }
    }
    __syncthreads();
    for (int q = tid; q < MTILE * 16; q += 320) {
        int row = q >> 4, c8 = q & 15;
        uint4 v = *(const uint4*)&xs[row * XSTRIDE + c8 * 8];
        ((uint4*)(g_hh + (size_t)(base + row) * F))[c8] = v;
    }
}

// ---------------- fused edge softmax + aggregation (gather, no max pass) ------
__device__ __forceinline__ float leaky_exp(float e) {
    e = e > 0.f ? e : NEG_SLOPE * e;
    return __expf(e);
}
__device__ __forceinline__ void acc_edge(float4& acc, float a, uint2 v) {
    float2 f01 = __half22float2(*(__half2*)&v.x);
    float2 f23 = __half22float2(*(__half2*)&v.y);
    acc.x = fmaf(a, f01.x, acc.x);
    acc.y = fmaf(a, f01.y, acc.y);
    acc.z = fmaf(a, f23.x, acc.z);
    acc.w = fmaf(a, f23.y, acc.w);
}

template<bool FP16OUT>
__global__ void gat_agg_kernel(const float* __restrict__ bias, float* __restrict__ out,
                               __half* __restrict__ out_h) {
    int warp = (blockIdx.x * blockDim.x + threadIdx.x) >> 5;
    int lane = threadIdx.x & 31;
    if (warp >= N_NODES) return;

    const unsigned start = g_off[warp];
    const int deg = (int)(g_off[warp + 1] - start);
    const int head = lane >> 3;
    const float erh = g_er[warp * 4 + head];
    const __half* __restrict__ hh = g_hh;

    float4 acc = make_float4(0.f, 0.f, 0.f, 0.f);
    float denom = 0.f;
    int i = 0;
    for (; i + 8 <= deg; i += 8) {
        int s[8];
        #pragma unroll
        for (int u = 0; u < 8; u++) s[u] = g_csr_src[start + i + u];
        float a[8];
        uint2 v[8];
        #pragma unroll
        for (int u = 0; u < 8; u++) {
            a[u] = g_el[s[u] * 4 + head];
            v[u] = *(const uint2*)(hh + (size_t)s[u] * F + lane * 4);
        }
        #pragma unroll
        for (int u = 0; u < 8; u++) {
            a[u] = leaky_exp(a[u] + erh);
            denom += a[u];
            acc_edge(acc, a[u], v[u]);
        }
    }
    for (; i < deg; i++) {
        int s0 = g_csr_src[start + i];
        float a0 = leaky_exp(g_el[s0 * 4 + head] + erh);
        uint2 v0 = *(const uint2*)(hh + (size_t)s0 * F + lane * 4);
        denom += a0;
        acc_edge(acc, a0, v0);
    }

    const float inv = 1.0f / fmaxf(denom, 1e-9f);
    const float4 b4 = ((const float4*)bias)[lane];
    float4 r;
    r.x = acc.x * inv + b4.x; r.x = r.x > 0.f ? r.x : expm1f(r.x);
    r.y = acc.y * inv + b4.y; r.y = r.y > 0.f ? r.y : expm1f(r.y);
    r.z = acc.z * inv + b4.z; r.z = r.z > 0.f ? r.z : expm1f(r.z);
    r.w = acc.w * inv + b4.w; r.w = r.w > 0.f ? r.w : expm1f(r.w);

    if (FP16OUT) {
        uint2 u;
        u.x = pack_h2(r.x, r.y); u.y = pack_h2(r.z, r.w);
        *(uint2*)(out_h + (size_t)warp * F + lane * 4) = u;
    } else {
        *(float4*)(out + (size_t)warp * F + lane * 4) = r;
    }
}

// ---------------- host orchestration -----------------------------------------

extern "C" void kernel_launch(void* const* d_in, const int* in_sizes, int n_in,
                              void* d_out, int out_size) {
    const float* features = (const float*)d_in[0];
    const int*   src      = (const int*)  d_in[1];
    const int*   dst      = (const int*)  d_in[2];
    const float* W1       = (const float*)d_in[3];
    const float* al1      = (const float*)d_in[4];
    const float* ar1      = (const float*)d_in[5];
    const float* b1       = (const float*)d_in[6];
    const float* W2       = (const float*)d_in[7];
    const float* al2      = (const float*)d_in[8];
    const float* ar2      = (const float*)d_in[9];
    const float* b2       = (const float*)d_in[10];
    float* out = (float*)d_out;

    __half* xh = nullptr;  cudaGetSymbolAddress((void**)&xh,  g_xh);
    __half* x2h = nullptr; cudaGetSymbolAddress((void**)&x2h, g_x2h);

    // slot 4 = gemm1 (ncu capture target)
    conv_half_kernel<<<(N_NODES * F / 4 + 255) / 256, 256>>>(features);   // 1
    bfrag_kernel<<<8, 256>>>(W1);                                         // 2
    hist_kernel<<<(N_EDGES + 255) / 256, 256>>>(dst);                     // 3
    gemm_mma_kernel<<<N_NODES / MTILE, 320>>>(xh, al1, ar1);              // 4 <- profiled
    scan1_kernel<<<NSCAN, SCAN_BLK>>>();                                  // 5
    scan2_kernel<<<1, 128>>>();                                           // 6
    scan3_kernel<<<NSCAN, SCAN_BLK>>>();                                  // 7
    scatter_kernel<<<(N_EDGES + 255) / 256, 256>>>(src, dst);             // 8
    gat_agg_kernel<true><<<(N_NODES * 32 + 255) / 256, 256>>>(b1, nullptr, x2h);  // 9
    bfrag_kernel<<<8, 256>>>(W2);                                         // 10
    gemm_mma_kernel<<<N_NODES / MTILE, 320>>>(x2h, al2, ar2);             // 11
    gat_agg_kernel<false><<<(N_NODES * 32 + 255) / 256, 256>>>(b2, out, nullptr); // 12
}